// round 6
// baseline (speedup 1.0000x reference)
#include <cuda_runtime.h>
#include <cuda_fp16.h>
#include <cstdint>
#include <math.h>

// Problem constants: N=8, S=8192, C=1, K=1024, V=64
#define NS_TOTAL 65536
#define VDIM 64
#define KCW 1024
#define BM 128
#define THREADS 512
#define EPS 4.0e-3f

// ---- smem layout (bytes) ----
#define SM_EH    0        // half2 [64][512] pair table (131072)
#define SM_XH    131072   // half2 [64][128] (x,x) duplicated (32768)
#define SM_XF    163840   // fp32 [128][65] padded (33280)
#define SM_EN    197120   // fp32 [1024] (4096)
#define SM_XN    201216   // fp32 [128] (512)
#define SM_CNT   201728   // int  [128] (512)
#define SM_CAND  202240   // u16  [128][16] (4096)
#define SM_AMIN  206336   // int  [128] (512)
#define SM_RSUM  206848   // fp32 [128] (512)
#define SMEM_BYTES 207360

typedef unsigned int uint;

__device__ float g_en[KCW];
__device__ int   g_counts[KCW];
__device__ uint  g_eh[VDIM * KCW / 2];     // half2 pairs: [v][kp] = (e[2kp][v], e[2kp+1][v])
__device__ int   g_nflag;
__device__ int   g_flagrows[NS_TOTAL];

// ---------------------------------------------------------------------------
__device__ __forceinline__ uint hfma2u(uint a, uint b, uint c) {
    __half2 r = __hfma2(*(__half2*)&a, *(__half2*)&b, *(__half2*)&c);
    return *(uint*)&r;
}
__device__ __forceinline__ float lo_f(uint h) { return __low2float(*(__half2*)&h); }
__device__ __forceinline__ float hi_f(uint h) { return __high2float(*(__half2*)&h); }

// ---------------------------------------------------------------------------
// Kernel 1: prep — exact en (sequential mul+add, v ascending), half2 pair
// table for E, zero histogram/flags
// ---------------------------------------------------------------------------
__global__ void vq_prep_kernel(const float* __restrict__ emb) {
    int t = blockIdx.x * blockDim.x + threadIdx.x;   // 0..1023
    if (t >= KCW) return;
    // exact codeword norm
    {
        const float* e = emb + (size_t)t * VDIM;
        float acc = 0.0f;
        #pragma unroll 8
        for (int v = 0; v < VDIM; v++)
            acc = __fadd_rn(acc, __fmul_rn(e[v], e[v]));
        g_en[t]     = acc;
        g_counts[t] = 0;
        if (t == 0) g_nflag = 0;
    }
    // pair table: thread t -> v = t&63, kp block = (t>>6)*32..+31
    int v  = t & 63;
    int kg = t >> 6;
    #pragma unroll 4
    for (int j = 0; j < 32; j++) {
        int kp = kg * 32 + j;
        float lo = emb[(size_t)(2 * kp)     * VDIM + v];
        float hi = emb[(size_t)(2 * kp + 1) * VDIM + v];
        __half2 p = __halves2half2(__float2half_rn(lo), __float2half_rn(hi));
        g_eh[v * 512 + kp] = *(uint*)&p;
    }
}

// ---------------------------------------------------------------------------
// Kernel 2: half2 filter GEMM (single sweep, streaming threshold) + exact
// rescore + outputs. grid 512 x 512 threads, 1 CTA/SM.
// thread tile: 4 rows x 16 codewords (8 half2 pairs)
// ---------------------------------------------------------------------------
__global__ __launch_bounds__(THREADS, 1)
void vq_half_kernel(const float* __restrict__ x, const float* __restrict__ emb,
                    float* __restrict__ out0, float* __restrict__ out1,
                    float* __restrict__ out2) {
    extern __shared__ char sm[];
    uint*  eh     = (uint*)(sm + SM_EH);
    uint*  xh     = (uint*)(sm + SM_XH);
    float* xf     = (float*)(sm + SM_XF);
    float* en_s   = (float*)(sm + SM_EN);
    float* xn_s   = (float*)(sm + SM_XN);
    int*   rowcnt = (int*)(sm + SM_CNT);
    unsigned short* cand = (unsigned short*)(sm + SM_CAND);
    int*   amin_s = (int*)(sm + SM_AMIN);
    float* rsum   = (float*)(sm + SM_RSUM);

    const int tid = threadIdx.x;
    const int tx  = tid & 15;            // codeword-pair group
    const int tyy = tid >> 4;            // 0..31: row group (rows tyy + 32*i)
    const int row0 = blockIdx.x * BM;

    // ---- load x tile: fp32 padded + half2(x,x) v-major ----
    const float4* x4 = reinterpret_cast<const float4*>(x) + (size_t)row0 * (VDIM / 4);
    #pragma unroll
    for (int t = 0; t < 4; t++) {
        int idx = tid + t * THREADS;     // 2048 float4
        int r   = idx >> 4;
        int v4  = idx & 15;
        float4 f = x4[idx];
        float* d = xf + r * 65 + v4 * 4;
        d[0] = f.x; d[1] = f.y; d[2] = f.z; d[3] = f.w;
        __half2 h0 = __half2half2(__float2half_rn(f.x));
        __half2 h1 = __half2half2(__float2half_rn(f.y));
        __half2 h2 = __half2half2(__float2half_rn(f.z));
        __half2 h3 = __half2half2(__float2half_rn(f.w));
        xh[(v4 * 4 + 0) * 128 + r] = *(uint*)&h0;
        xh[(v4 * 4 + 1) * 128 + r] = *(uint*)&h1;
        xh[(v4 * 4 + 2) * 128 + r] = *(uint*)&h2;
        xh[(v4 * 4 + 3) * 128 + r] = *(uint*)&h3;
    }
    // ---- load E pair table (131072 B) + en ----
    {
        const uint4* src = reinterpret_cast<const uint4*>(g_eh);
        uint4* dst = reinterpret_cast<uint4*>(eh);
        #pragma unroll
        for (int t = 0; t < 16; t++) dst[tid + t * THREADS] = src[tid + t * THREADS];
        #pragma unroll
        for (int t = 0; t < 2; t++) en_s[tid + t * THREADS] = g_en[tid + t * THREADS];
    }
    if (tid < BM) { rowcnt[tid] = 0; rsum[tid] = 0.0f; }
    __syncthreads();

    // ---- exact xn per row (sequential mul+add, v ascending) ----
    if (tid < BM) {
        float acc = 0.0f;
        const float* xr = xf + tid * 65;
        #pragma unroll 8
        for (int v = 0; v < VDIM; v++)
            acc = __fadd_rn(acc, __fmul_rn(xr[v], xr[v]));
        xn_s[tid] = acc;
    }
    __syncthreads();

    // =================== single-sweep filter over 4 chunks ===================
    float rowmin[4];
    #pragma unroll
    for (int i = 0; i < 4; i++) rowmin[i] = 3.402823466e38f;

    #pragma unroll 1
    for (int c = 0; c < 4; c++) {
        uint acc[4][8];
        #pragma unroll
        for (int i = 0; i < 4; i++)
            #pragma unroll
            for (int m = 0; m < 8; m++) acc[i][m] = 0u;

        const uint* eb = eh + c * 128 + tx;
        const uint* xb = xh + tyy;
        #pragma unroll 8
        for (int v = 0; v < VDIM; v++) {
            uint ev[8];
            #pragma unroll
            for (int m = 0; m < 8; m++) ev[m] = eb[v * 512 + 16 * m];
            uint xv[4];
            #pragma unroll
            for (int i = 0; i < 4; i++) xv[i] = xb[v * 128 + 32 * i];
            #pragma unroll
            for (int i = 0; i < 4; i++)
                #pragma unroll
                for (int m = 0; m < 8; m++)
                    acc[i][m] = hfma2u(xv[i], ev[m], acc[i][m]);
        }

        // per-row chunk min, update running min, collect candidates
        #pragma unroll
        for (int i = 0; i < 4; i++) {
            int r = tyy + 32 * i;
            float cmin = 3.402823466e38f;
            #pragma unroll
            for (int m = 0; m < 8; m++) {
                int k0 = c * 256 + 32 * m + 2 * tx;
                float u0 = __fmaf_rn(-2.0f, lo_f(acc[i][m]), en_s[k0]);
                float u1 = __fmaf_rn(-2.0f, hi_f(acc[i][m]), en_s[k0 + 1]);
                cmin = fminf(cmin, fminf(u0, u1));
            }
            // reduce across the 16 lanes (half-warp) owning this row
            cmin = fminf(cmin, __shfl_xor_sync(0xffffffffu, cmin, 1));
            cmin = fminf(cmin, __shfl_xor_sync(0xffffffffu, cmin, 2));
            cmin = fminf(cmin, __shfl_xor_sync(0xffffffffu, cmin, 4));
            cmin = fminf(cmin, __shfl_xor_sync(0xffffffffu, cmin, 8));
            rowmin[i] = fminf(rowmin[i], cmin);
            float thr = rowmin[i] + EPS;
            #pragma unroll
            for (int m = 0; m < 8; m++) {
                int k0 = c * 256 + 32 * m + 2 * tx;
                float u0 = __fmaf_rn(-2.0f, lo_f(acc[i][m]), en_s[k0]);
                float u1 = __fmaf_rn(-2.0f, hi_f(acc[i][m]), en_s[k0 + 1]);
                if (u0 <= thr) {
                    int p = atomicAdd(&rowcnt[r], 1);
                    if (p < 16) cand[r * 16 + p] = (unsigned short)k0;
                }
                if (u1 <= thr) {
                    int p = atomicAdd(&rowcnt[r], 1);
                    if (p < 16) cand[r * 16 + p] = (unsigned short)(k0 + 1);
                }
            }
        }
    }
    __syncthreads();

    // ---- exact rescore (thread-per-row, reference rounding, lexicographic) ----
    if (tid < BM) {
        int cnt = rowcnt[tid];
        if (cnt <= 16) {
            float bv = 3.402823466e38f;
            int   bi = 1 << 30;
            const float* xr = xf + tid * 65;
            float xn = xn_s[tid];
            for (int cI = 0; cI < cnt; cI++) {
                int k = cand[tid * 16 + cI];
                const float* er = emb + (size_t)k * VDIM;
                float acc = 0.0f;
                #pragma unroll 16
                for (int v = 0; v < VDIM; v++)
                    acc = __fmaf_rn(xr[v], er[v], acc);
                float s = __fadd_rn(__fsub_rn(xn, __fmul_rn(2.0f, acc)), en_s[k]);
                if (s < bv || (s == bv && k < bi)) { bv = s; bi = k; }
            }
            amin_s[tid] = bi;
            atomicAdd(&g_counts[bi], 1);
        } else {
            int pos = atomicAdd(&g_nflag, 1);
            g_flagrows[pos] = row0 + tid;
            amin_s[tid] = -1;
        }
    }
    __syncthreads();

    // ---- outputs: out0 = fl(fl(o-x)+x); out1 = out2 = sum (x-o)^2 ----
    #pragma unroll 4
    for (int t = 0; t < 16; t++) {
        int i = t * THREADS + tid;       // 8192 elements; warp = half a row
        int r = i >> 6;
        int v = i & 63;
        int bi = amin_s[r];
        if (bi >= 0) {
            float o  = emb[(size_t)bi * VDIM + v];
            float xv = xf[r * 65 + v];
            float dd = __fsub_rn(xv, o);
            float sq = __fmul_rn(dd, dd);
            #pragma unroll
            for (int off = 16; off > 0; off >>= 1)
                sq += __shfl_down_sync(0xffffffffu, sq, off);
            if ((tid & 31) == 0) atomicAdd(&rsum[r], sq);   // 2 adds/row: order-invariant
            out0[(size_t)(row0 + r) * VDIM + v] = __fadd_rn(__fsub_rn(o, xv), xv);
        }
    }
    __syncthreads();
    if (tid < BM && amin_s[tid] >= 0) {
        float s = rsum[tid];
        out1[row0 + tid] = s;
        out2[row0 + tid] = s;
    }
}

// ---------------------------------------------------------------------------
// Kernel 3: fallback for shortlist-overflow rows (full exact 1024-scan)
// ---------------------------------------------------------------------------
__global__ void vq_fix_kernel(const float* __restrict__ x, const float* __restrict__ emb,
                              float* __restrict__ out0, float* __restrict__ out1,
                              float* __restrict__ out2) {
    __shared__ float xrow[8][65];
    int nf  = g_nflag;
    int wid = threadIdx.x >> 5;
    int lid = threadIdx.x & 31;
    for (int f = blockIdx.x * 8 + wid; f < nf; f += gridDim.x * 8) {
        int row = g_flagrows[f];
        const float* xr = x + (size_t)row * VDIM;
        xrow[wid][lid]      = xr[lid];
        xrow[wid][lid + 32] = xr[lid + 32];
        __syncwarp();
        float xn = 0.0f;
        #pragma unroll 8
        for (int v = 0; v < VDIM; v++)
            xn = __fadd_rn(xn, __fmul_rn(xrow[wid][v], xrow[wid][v]));
        float bv = 3.402823466e38f;
        int   bi = 1 << 30;
        for (int j = 0; j < 32; j++) {
            int k = j * 32 + lid;
            const float* er = emb + (size_t)k * VDIM;
            float acc = 0.0f;
            #pragma unroll 16
            for (int v = 0; v < VDIM; v++)
                acc = __fmaf_rn(xrow[wid][v], er[v], acc);
            float s = __fadd_rn(__fsub_rn(xn, __fmul_rn(2.0f, acc)), g_en[k]);
            if (s < bv || (s == bv && k < bi)) { bv = s; bi = k; }
        }
        #pragma unroll
        for (int off = 16; off > 0; off >>= 1) {
            float ov = __shfl_down_sync(0xffffffffu, bv, off);
            int   oi = __shfl_down_sync(0xffffffffu, bi, off);
            if (ov < bv || (ov == bv && oi < bi)) { bv = ov; bi = oi; }
        }
        bi = __shfl_sync(0xffffffffu, bi, 0);
        if (lid == 0) atomicAdd(&g_counts[bi], 1);
        float sq = 0.0f;
        #pragma unroll
        for (int h = 0; h < 2; h++) {
            int v = lid + 32 * h;
            float o  = emb[(size_t)bi * VDIM + v];
            float xv = xrow[wid][v];
            float dd = __fsub_rn(xv, o);
            sq += dd * dd;
            out0[(size_t)row * VDIM + v] = __fadd_rn(__fsub_rn(o, xv), xv);
        }
        #pragma unroll
        for (int off = 16; off > 0; off >>= 1)
            sq += __shfl_down_sync(0xffffffffu, sq, off);
        if (lid == 0) { out1[row] = sq; out2[row] = sq; }
        __syncwarp();
    }
}

// ---------------------------------------------------------------------------
// Kernel 4: entropy of the histogram
// ---------------------------------------------------------------------------
__global__ void vq_entropy_kernel(float* __restrict__ ent) {
    __shared__ float warpsum[32];
    int k = threadIdx.x;
    int c = g_counts[k];
    float term = 0.0f;
    if (c > 0) {
        float p = (float)c * (1.0f / 65536.0f);
        term = -p * logf(p);
    }
    #pragma unroll
    for (int off = 16; off > 0; off >>= 1)
        term += __shfl_down_sync(0xffffffffu, term, off);
    int lane = k & 31, wid = k >> 5;
    if (lane == 0) warpsum[wid] = term;
    __syncthreads();
    if (wid == 0) {
        float s = warpsum[lane];
        #pragma unroll
        for (int off = 16; off > 0; off >>= 1)
            s += __shfl_down_sync(0xffffffffu, s, off);
        if (lane == 0) *ent = s;
    }
}

// ---------------------------------------------------------------------------
extern "C" void kernel_launch(void* const* d_in, const int* in_sizes, int n_in,
                              void* d_out, int out_size) {
    const float* x;
    const float* emb;
    if (in_sizes[0] == NS_TOTAL * VDIM) {
        x   = (const float*)d_in[0];
        emb = (const float*)d_in[1];
    } else {
        x   = (const float*)d_in[1];
        emb = (const float*)d_in[0];
    }

    float* out0 = (float*)d_out;
    float* out1 = out0 + (size_t)NS_TOTAL * VDIM;
    float* out2 = out1 + NS_TOTAL;
    float* ent  = out2 + NS_TOTAL;

    cudaFuncSetAttribute(vq_half_kernel,
                         cudaFuncAttributeMaxDynamicSharedMemorySize, SMEM_BYTES);

    vq_prep_kernel<<<4, 256>>>(emb);
    vq_half_kernel<<<512, THREADS, SMEM_BYTES>>>(x, emb, out0, out1, out2);
    vq_fix_kernel<<<32, 256>>>(x, emb, out0, out1, out2);
    vq_entropy_kernel<<<1, 1024>>>(ent);
}